// round 7
// baseline (speedup 1.0000x reference)
#include <cuda_runtime.h>

#define N   512
#define DIM 384
#define BK  32
#define NTL 12          // DIM / BK

// Scratch (device globals per allocation-free rule)
__device__ float    g_D[N * N];    // pairwise distances, diag = 1e6
__device__ float    g_prec[N];     // per-query soft precision
__device__ unsigned g_ctr1;        // monotonic ticket: grid barrier (replay-safe)
__device__ unsigned g_ctr2;        // monotonic ticket: completion count

__device__ __forceinline__ float sigmoidf_(float x) {
    if (x >= 0.f) { float e = __expf(-x); return 1.f / (1.f + e); }
    float e = __expf(x); return e / (1.f + e);
}
__device__ __forceinline__ float sig_sat(float x) {
    if (x > 18.f)  return 1.f;     // err < 1.6e-8
    if (x < -18.f) return 0.f;
    float e = __expf(-x);
    return 1.f / (1.f + e);
}

// smem layout (floats): phase1 sa[32*36] | sb[32*68] | snA[32] | snB[64] | swr[8]
// phase2 aliases the same buffer: sd[4*512] | slab[512]
#define SA_STRIDE 36
#define SB_STRIDE 68
#define SMEM_FLOATS (32*SA_STRIDE + 32*SB_STRIDE + 32 + 64 + 8)

__global__ void __launch_bounds__(128, 1)
k_fused(const float* __restrict__ emb, const int* __restrict__ labels,
        float* __restrict__ out)
{
    __shared__ float smem[SMEM_FLOATS];
    __shared__ int s_done;

    const int t = threadIdx.x;
    const int b = blockIdx.x;

    // ================= Phase 1: fused Gram -> distance tile =================
    {
        float* sa  = smem;                       // k-major [k][r], stride 36
        float* sb  = smem + 32 * SA_STRIDE;      // k-major [k][r], stride 68
        float* snA = sb + 32 * SB_STRIDE;        // 32 row norms (q side)
        float* snB = snA + 32;                   // 64 row norms (m side)

        const int m0 = (b & 7) * 64;
        const int q0 = (b >> 3) * 32;
        const int rA = t >> 2, cA = (t & 3) * 8;
        const int rB = t >> 1, cB = (t & 1) * 16;
        const float* pA = emb + (size_t)(q0 + rA) * DIM + cA;
        const float* pB = emb + (size_t)(m0 + rB) * DIM + cB;
        const int ty = t >> 4, tx = t & 15;

        float acc[4][4];
#pragma unroll
        for (int i = 0; i < 4; i++)
#pragma unroll
            for (int j = 0; j < 4; j++) acc[i][j] = 0.f;
        float nA = 0.f, nB = 0.f;

        float4 a0, a1, b0, b1, b2, b3;
        a0 = *(const float4*)(pA);      a1 = *(const float4*)(pA + 4);
        b0 = *(const float4*)(pB);      b1 = *(const float4*)(pB + 4);
        b2 = *(const float4*)(pB + 8);  b3 = *(const float4*)(pB + 12);

#pragma unroll 1
        for (int tt = 0; tt < NTL; tt++) {
            // norms (each element touched exactly once across tiles)
            nA = fmaf(a0.x,a0.x,fmaf(a0.y,a0.y,fmaf(a0.z,a0.z,fmaf(a0.w,a0.w,nA))));
            nA = fmaf(a1.x,a1.x,fmaf(a1.y,a1.y,fmaf(a1.z,a1.z,fmaf(a1.w,a1.w,nA))));
            nB = fmaf(b0.x,b0.x,fmaf(b0.y,b0.y,fmaf(b0.z,b0.z,fmaf(b0.w,b0.w,nB))));
            nB = fmaf(b1.x,b1.x,fmaf(b1.y,b1.y,fmaf(b1.z,b1.z,fmaf(b1.w,b1.w,nB))));
            nB = fmaf(b2.x,b2.x,fmaf(b2.y,b2.y,fmaf(b2.z,b2.z,fmaf(b2.w,b2.w,nB))));
            nB = fmaf(b3.x,b3.x,fmaf(b3.y,b3.y,fmaf(b3.z,b3.z,fmaf(b3.w,b3.w,nB))));
            // transpose into smem
            sa[(cA+0)*SA_STRIDE + rA] = a0.x; sa[(cA+1)*SA_STRIDE + rA] = a0.y;
            sa[(cA+2)*SA_STRIDE + rA] = a0.z; sa[(cA+3)*SA_STRIDE + rA] = a0.w;
            sa[(cA+4)*SA_STRIDE + rA] = a1.x; sa[(cA+5)*SA_STRIDE + rA] = a1.y;
            sa[(cA+6)*SA_STRIDE + rA] = a1.z; sa[(cA+7)*SA_STRIDE + rA] = a1.w;
            sb[(cB+ 0)*SB_STRIDE + rB] = b0.x; sb[(cB+ 1)*SB_STRIDE + rB] = b0.y;
            sb[(cB+ 2)*SB_STRIDE + rB] = b0.z; sb[(cB+ 3)*SB_STRIDE + rB] = b0.w;
            sb[(cB+ 4)*SB_STRIDE + rB] = b1.x; sb[(cB+ 5)*SB_STRIDE + rB] = b1.y;
            sb[(cB+ 6)*SB_STRIDE + rB] = b1.z; sb[(cB+ 7)*SB_STRIDE + rB] = b1.w;
            sb[(cB+ 8)*SB_STRIDE + rB] = b2.x; sb[(cB+ 9)*SB_STRIDE + rB] = b2.y;
            sb[(cB+10)*SB_STRIDE + rB] = b2.z; sb[(cB+11)*SB_STRIDE + rB] = b2.w;
            sb[(cB+12)*SB_STRIDE + rB] = b3.x; sb[(cB+13)*SB_STRIDE + rB] = b3.y;
            sb[(cB+14)*SB_STRIDE + rB] = b3.z; sb[(cB+15)*SB_STRIDE + rB] = b3.w;
            __syncthreads();

            // prefetch next tile (overlaps with compute below)
            if (tt + 1 < NTL) {
                const float* qA = pA + (tt + 1) * BK;
                const float* qB = pB + (tt + 1) * BK;
                a0 = *(const float4*)(qA);      a1 = *(const float4*)(qA + 4);
                b0 = *(const float4*)(qB);      b1 = *(const float4*)(qB + 4);
                b2 = *(const float4*)(qB + 8);  b3 = *(const float4*)(qB + 12);
            }

#pragma unroll
            for (int k = 0; k < BK; k++) {
                float4 av = *(const float4*)&sa[k * SA_STRIDE + ty * 4];
                float4 bv = *(const float4*)&sb[k * SB_STRIDE + tx * 4];
                acc[0][0] = fmaf(av.x, bv.x, acc[0][0]);
                acc[0][1] = fmaf(av.x, bv.y, acc[0][1]);
                acc[0][2] = fmaf(av.x, bv.z, acc[0][2]);
                acc[0][3] = fmaf(av.x, bv.w, acc[0][3]);
                acc[1][0] = fmaf(av.y, bv.x, acc[1][0]);
                acc[1][1] = fmaf(av.y, bv.y, acc[1][1]);
                acc[1][2] = fmaf(av.y, bv.z, acc[1][2]);
                acc[1][3] = fmaf(av.y, bv.w, acc[1][3]);
                acc[2][0] = fmaf(av.z, bv.x, acc[2][0]);
                acc[2][1] = fmaf(av.z, bv.y, acc[2][1]);
                acc[2][2] = fmaf(av.z, bv.z, acc[2][2]);
                acc[2][3] = fmaf(av.z, bv.w, acc[2][3]);
                acc[3][0] = fmaf(av.w, bv.x, acc[3][0]);
                acc[3][1] = fmaf(av.w, bv.y, acc[3][1]);
                acc[3][2] = fmaf(av.w, bv.z, acc[3][2]);
                acc[3][3] = fmaf(av.w, bv.w, acc[3][3]);
            }
            __syncthreads();
        }

        // finish norms within lane groups sharing a row
        nA += __shfl_xor_sync(0xffffffffu, nA, 1);
        nA += __shfl_xor_sync(0xffffffffu, nA, 2);
        if ((t & 3) == 0) snA[rA] = nA;
        nB += __shfl_xor_sync(0xffffffffu, nB, 1);
        if ((t & 1) == 0) snB[rB] = nB;
        __syncthreads();

        // epilogue: distances, diag = 1e6
#pragma unroll
        for (int i = 0; i < 4; i++) {
            int q = q0 + ty * 4 + i;
            int mb = m0 + tx * 4;
            float nq = snA[ty * 4 + i];
            float dv[4];
#pragma unroll
            for (int c = 0; c < 4; c++) {
                float d2 = nq + snB[tx * 4 + c] - 2.f * acc[i][c];
                dv[c] = (q == mb + c) ? 1e6f : sqrtf(fmaxf(d2, 1e-12f));
            }
            *(float4*)&g_D[(size_t)q * N + mb] = make_float4(dv[0], dv[1], dv[2], dv[3]);
        }
    }

    // ================= Grid barrier (replay-safe monotonic ticket) =================
    if (t == 0) {
        __threadfence();
        unsigned tk = atomicAdd(&g_ctr1, 1u);
        unsigned target = (tk / 128u) * 128u + 128u;
        while (atomicAdd(&g_ctr1, 0u) < target) __nanosleep(64);
        __threadfence();
    }
    __syncthreads();

    // ================= Phase 2: warp-per-query soft precision =================
    {
        float* sd   = smem;                      // 4 rows x 512 floats
        int*   slab = (int*)(smem + 4 * N);      // 512 labels

        const int q0b = b * 4;
        // 4 consecutive rows of g_D = 2048 floats = 512 float4s -> 4 iters @128 thr
        const float4* src = (const float4*)(g_D + (size_t)q0b * N);
        float4* dst = (float4*)sd;
#pragma unroll
        for (int i = 0; i < 4; i++) dst[t + 128 * i] = __ldcg(&src[t + 128 * i]);
        ((int4*)slab)[t] = ((const int4*)labels)[t];
        __syncthreads();

        const int lane = t & 31;
        const int w    = t >> 5;
        const int q    = q0b + w;
        const int lq   = slab[q];
        const float* row = sd + w * N;

        float num = 0.f;
        int   cnt = 0;
#pragma unroll 1
        for (int c = 0; c < 16; c++) {
            int j = c * 32 + lane;
            bool f = (j != q) && (slab[j] == lq);
            unsigned bm = __ballot_sync(0xffffffffu, f);
            cnt += __popc(bm);
            while (bm) {                         // ascending j: deterministic
                int bit = __ffs(bm) - 1;
                bm &= bm - 1;
                float dj = row[c * 32 + bit];
                float part = 0.f;
#pragma unroll
                for (int i = 0; i < 16; i++)
                    part += sig_sat((dj - row[lane + 32 * i]) * 100.0f); // 1/T2
#pragma unroll
                for (int o = 16; o; o >>= 1)
                    part += __shfl_xor_sync(0xffffffffu, part, o);
                num += sigmoidf_(5.0f - part);   // K=5, T1=1
            }
        }
        if (lane == 0)
            g_prec[q] = num / fminf((float)cnt, 5.0f);  // 0/0 -> NaN like reference
    }

    // ================= Phase 3: last-arriving block does the mean =================
    __syncthreads();
    if (t == 0) {
        __threadfence();
        unsigned tk = atomicAdd(&g_ctr2, 1u);
        s_done = ((tk & 127u) == 127u) ? 1 : 0;
    }
    __syncthreads();

    if (s_done) {
        __threadfence();
        float v = 0.f;
#pragma unroll
        for (int i = 0; i < 4; i++) v += __ldcg(&g_prec[t + 128 * i]);
        const int lane = t & 31;
        const int w    = t >> 5;
#pragma unroll
        for (int o = 16; o; o >>= 1)
            v += __shfl_xor_sync(0xffffffffu, v, o);
        float* swr = smem + 32 * SA_STRIDE + 32 * SB_STRIDE + 96;
        if (lane == 0) swr[w] = v;
        __syncthreads();
        if (t == 0)
            out[0] = 1.0f - (swr[0] + swr[1] + swr[2] + swr[3]) / (float)N;
    }
}

extern "C" void kernel_launch(void* const* d_in, const int* in_sizes, int n_in,
                              void* d_out, int out_size) {
    const float* emb    = (const float*)d_in[0];
    const int*   labels = (const int*)d_in[1];
    k_fused<<<128, 128>>>(emb, labels, (float*)d_out);
}

// round 8
// speedup vs baseline: 2.0480x; 2.0480x over previous
#include <cuda_runtime.h>

#define N   512
#define DIM 384
#define BK  32
#define NTL 12          // DIM / BK
typedef unsigned long long ull;

// Scratch (device globals per allocation-free rule)
__device__ float    g_D[N * N];    // pairwise distances, diag = 1e6
__device__ float    g_prec[N];     // per-query soft precision
__device__ unsigned g_ctr;         // monotonic ticket (replay-safe: +128 per replay)

// Branchless full-range sigmoid: exp underflow gives exact 0/1 saturation,
// no divergent branches, args up to +-1e8 are safe (exp(-1e8) -> 0).
__device__ __forceinline__ float sigmoid_nb(float x) {
    float e = __expf(-fabsf(x));
    float p = __fdividef(1.f, 1.f + e);
    return (x >= 0.f) ? p : 1.f - p;
}

__device__ __forceinline__ void fma2(ull& d, ull a, ull b) {
    asm("fma.rn.f32x2 %0, %1, %2, %0;" : "+l"(d) : "l"(a), "l"(b));
}
__device__ __forceinline__ float2 unpack2(ull v) {
    float2 r;
    asm("mov.b64 {%0, %1}, %2;" : "=f"(r.x), "=f"(r.y) : "l"(v));
    return r;
}

// ---------------- Kernel 1: fused Gram -> distance matrix (FFMA2) ----------------
// BM=32 (q) x BN=64 (m), BK=32, 256 threads, 2x4 micro-tile via f32x2.
// A-tile stored DUPLICATED in smem: sa[k][2r],[2r+1] = A[r][k], so one LDS.128
// yields (a_r0,a_r0,a_r1,a_r1) = two ready f32x2 broadcast operands.
#define SA_STR 68   // floats per k-row (64 used + pad); 272B row: 16B-aligned
#define SB_STR 68

__global__ void __launch_bounds__(256, 1) k_gram(const float* __restrict__ emb) {
    __shared__ __align__(16) float sa[BK * SA_STR];
    __shared__ __align__(16) float sb[BK * SB_STR];
    __shared__ float snA[32];
    __shared__ float snB[64];

    const int t  = threadIdx.x;
    const int q0 = blockIdx.y * 32;
    const int m0 = blockIdx.x * 64;
    const int rA = t >> 3, cA = (t & 7) * 4;   // A tile: 1 float4/thread
    const int rB = t >> 2, cB = (t & 3) * 8;   // B tile: 2 float4/thread
    const float* pA = emb + (size_t)(q0 + rA) * DIM + cA;
    const float* pB = emb + (size_t)(m0 + rB) * DIM + cB;
    const int tx = t & 15, ty = t >> 4;

    ull acc00 = 0, acc01 = 0, acc10 = 0, acc11 = 0;
    float nA = 0.f, nB = 0.f;

    float4 a0 = *(const float4*)pA;
    float4 b0 = *(const float4*)pB;
    float4 b1 = *(const float4*)(pB + 4);

#pragma unroll 1
    for (int tt = 0; tt < NTL; tt++) {
        // norms: each element touched exactly once across all tiles
        nA = fmaf(a0.x,a0.x,fmaf(a0.y,a0.y,fmaf(a0.z,a0.z,fmaf(a0.w,a0.w,nA))));
        nB = fmaf(b0.x,b0.x,fmaf(b0.y,b0.y,fmaf(b0.z,b0.z,fmaf(b0.w,b0.w,nB))));
        nB = fmaf(b1.x,b1.x,fmaf(b1.y,b1.y,fmaf(b1.z,b1.z,fmaf(b1.w,b1.w,nB))));

        // A duplicated k-major stores (float2 = STS.64)
        *(float2*)&sa[(cA+0)*SA_STR + 2*rA] = make_float2(a0.x, a0.x);
        *(float2*)&sa[(cA+1)*SA_STR + 2*rA] = make_float2(a0.y, a0.y);
        *(float2*)&sa[(cA+2)*SA_STR + 2*rA] = make_float2(a0.z, a0.z);
        *(float2*)&sa[(cA+3)*SA_STR + 2*rA] = make_float2(a0.w, a0.w);
        // B k-major stores
        sb[(cB+0)*SB_STR + rB] = b0.x; sb[(cB+1)*SB_STR + rB] = b0.y;
        sb[(cB+2)*SB_STR + rB] = b0.z; sb[(cB+3)*SB_STR + rB] = b0.w;
        sb[(cB+4)*SB_STR + rB] = b1.x; sb[(cB+5)*SB_STR + rB] = b1.y;
        sb[(cB+6)*SB_STR + rB] = b1.z; sb[(cB+7)*SB_STR + rB] = b1.w;
        __syncthreads();

        if (tt + 1 < NTL) {   // register prefetch hides LDG under compute
            a0 = *(const float4*)(pA + (tt + 1) * BK);
            b0 = *(const float4*)(pB + (tt + 1) * BK);
            b1 = *(const float4*)(pB + (tt + 1) * BK + 4);
        }

#pragma unroll
        for (int k = 0; k < BK; k++) {
            ulonglong2 aav = *(const ulonglong2*)&sa[k * SA_STR + 4 * ty];
            ulonglong2 bbv = *(const ulonglong2*)&sb[k * SB_STR + 4 * tx];
            fma2(acc00, aav.x, bbv.x);
            fma2(acc01, aav.x, bbv.y);
            fma2(acc10, aav.y, bbv.x);
            fma2(acc11, aav.y, bbv.y);
        }
        __syncthreads();
    }

    // finish norms within lane-groups sharing a row
    nA += __shfl_xor_sync(0xffffffffu, nA, 1);
    nA += __shfl_xor_sync(0xffffffffu, nA, 2);
    nA += __shfl_xor_sync(0xffffffffu, nA, 4);
    if ((t & 7) == 0) snA[rA] = nA;
    nB += __shfl_xor_sync(0xffffffffu, nB, 1);
    nB += __shfl_xor_sync(0xffffffffu, nB, 2);
    if ((t & 3) == 0) snB[rB] = nB;
    __syncthreads();

    // epilogue: distances, diag = 1e6
    float2 c00 = unpack2(acc00), c01 = unpack2(acc01);
    float2 c10 = unpack2(acc10), c11 = unpack2(acc11);
    float accs[2][4] = {{c00.x, c00.y, c01.x, c01.y},
                        {c10.x, c10.y, c11.x, c11.y}};
#pragma unroll
    for (int i = 0; i < 2; i++) {
        int q  = q0 + 2 * ty + i;
        int mb = m0 + 4 * tx;
        float nq = snA[2 * ty + i];
        float dv[4];
#pragma unroll
        for (int c = 0; c < 4; c++) {
            float d2 = nq + snB[4 * tx + c] - 2.f * accs[i][c];
            dv[c] = (q == mb + c) ? 1e6f : sqrtf(fmaxf(d2, 1e-12f));
        }
        *(float4*)&g_D[(size_t)q * N + mb] = make_float4(dv[0], dv[1], dv[2], dv[3]);
    }
}

// ---------------- Kernel 2: soft precision, 4 queries/block ----------------
// 128 blocks x 512 threads. Warp w: query (w&3), j-quarter (w>>2).
// Atomic tail cut 512 -> 128 RMWs. Last-arriving block does fixed-order mean.
__global__ void __launch_bounds__(512) k_prec(const int* __restrict__ labels,
                                              float* __restrict__ out) {
    __shared__ float sd[4][N];     // 4 distance rows
    __shared__ int   slab[N];
    __shared__ float wnum[16];
    __shared__ int   wcnt[16];
    __shared__ float swr[16];
    __shared__ int   s_done;

    const int t    = threadIdx.x;
    const int lane = t & 31;
    const int w    = t >> 5;
    const int q0   = blockIdx.x * 4;

    // 4 rows = 2048 floats = 512 float4 -> exactly 1 per thread
    ((float4*)sd)[t] = __ldcg(&((const float4*)(g_D + (size_t)q0 * N))[t]);
    if (t < 128) ((int4*)slab)[t] = ((const int4*)labels)[t];
    __syncthreads();

    const int   qsel = w & 3;
    const int   q    = q0 + qsel;
    const int   lq   = slab[q];
    const float* row = sd[qsel];
    const int   jb   = (w >> 2) * 128;

    float num = 0.f;
    int   cnt = 0;
#pragma unroll
    for (int c = 0; c < 4; c++) {
        int j = jb + c * 32 + lane;
        bool f = (j != q) && (slab[j] == lq);
        unsigned bm = __ballot_sync(0xffffffffu, f);
        cnt += __popc(bm);
        while (bm) {                         // ascending j: deterministic
            int bit = __ffs(bm) - 1;
            bm &= bm - 1;
            float dj = row[jb + c * 32 + bit];
            float part = 0.f;
#pragma unroll
            for (int i = 0; i < 16; i++)
                part += sigmoid_nb((dj - row[lane + 32 * i]) * 100.0f); // 1/T2
#pragma unroll
            for (int o = 16; o; o >>= 1)
                part += __shfl_xor_sync(0xffffffffu, part, o);
            num += sigmoid_nb(5.0f - part);  // K=5, T1=1
        }
    }
    if (lane == 0) { wnum[w] = num; wcnt[w] = cnt; }
    __syncthreads();

    if (t < 4) {   // thread t finalizes query q0+t in fixed quarter order
        float s = wnum[t] + wnum[4 + t] + wnum[8 + t] + wnum[12 + t];
        int   c = wcnt[t] + wcnt[4 + t] + wcnt[8 + t] + wcnt[12 + t];
        g_prec[q0 + t] = s / fminf((float)c, 5.0f);  // 0/0 -> NaN like reference
    }
    __syncthreads();

    if (t == 0) {
        __threadfence();
        unsigned tk = atomicAdd(&g_ctr, 1u);
        s_done = ((tk & 127u) == 127u) ? 1 : 0;
    }
    __syncthreads();

    if (s_done) {    // last block: deterministic fixed-order mean
        __threadfence();
        float v = __ldcg(&g_prec[t]);        // 512 threads, 512 values
#pragma unroll
        for (int o = 16; o; o >>= 1)
            v += __shfl_xor_sync(0xffffffffu, v, o);
        if (lane == 0) swr[w] = v;
        __syncthreads();
        if (t == 0) {
            float s = 0.f;
#pragma unroll
            for (int i = 0; i < 16; i++) s += swr[i];
            out[0] = 1.0f - s / (float)N;
        }
    }
}

extern "C" void kernel_launch(void* const* d_in, const int* in_sizes, int n_in,
                              void* d_out, int out_size) {
    const float* emb    = (const float*)d_in[0];
    const int*   labels = (const int*)d_in[1];
    k_gram<<<dim3(8, 16), 256>>>(emb);
    k_prec<<<128, 512>>>(labels, (float*)d_out);
}